// round 7
// baseline (speedup 1.0000x reference)
#include <cuda_runtime.h>
#include <cstdint>

#define NNZ   1000000
#define NROWS 500
#define MCOLS 50000
#define D     128
#define SCAN_BLOCKS 49   // ceil(50000/1024)
#define NTILES ((NNZ + 127) / 128)   // 7813
#define GRID_MAIN 148

// ---------------- scratch (device globals; no runtime allocation) ----------
__device__ float g_colmean[MCOLS * D];
__device__ float g_rowsum [NROWS * D];
__device__ float g_rowmean[NROWS * D];
__device__ float g_G[MCOLS * D];         // 0.25 * colmean @ W_n
__device__ float g_H[NROWS * D];         // 0.25 * rowmean @ W_m
__device__ float g_C[D];                 // 0.25*(gmean@W_both + all biases)
__device__ int   g_colcnt[MCOLS];
__device__ int   g_rowcnt[NROWS];
__device__ int   g_coloff[MCOLS + 1];
__device__ int   g_rowoff[NROWS + 1];
__device__ int   g_colcur[MCOLS];
__device__ int   g_rowcur[NROWS];
__device__ int   g_colids[NNZ];
__device__ int   g_rowids[NNZ];
__device__ int   g_partial[SCAN_BLOCKS];
__device__ int   g_poff[SCAN_BLOCKS + 1];
__device__ __align__(16) unsigned g_Wfmt[128 * 136];  // W_all tf32, [k][136] padded

__device__ __forceinline__ unsigned to_tf32(float f) {
    unsigned u;
    asm("cvt.rna.tf32.f32 %0, %1;" : "=r"(u) : "f"(f));
    return u;
}
__device__ __forceinline__ uint32_t smem_to_u32(const void* p) {
    uint32_t a;
    asm("{ .reg .u64 t; cvta.to.shared.u64 t, %1; cvt.u32.u64 %0, t; }" : "=r"(a) : "l"(p));
    return a;
}

// cp.async (Ampere+ PTX; arch-neutral, compiles on this target)
#define CP_ASYNC16(dst, src) \
    asm volatile("cp.async.cg.shared.global [%0], [%1], 16;" :: "r"(dst), "l"(src))
#define CP_ASYNC4(dst, src) \
    asm volatile("cp.async.ca.shared.global [%0], [%1], 4;" :: "r"(dst), "l"(src))
#define CP_COMMIT() asm volatile("cp.async.commit_group;" ::: "memory")
#define CP_WAIT1()  asm volatile("cp.async.wait_group 1;"  ::: "memory")

// ---------------- zeroing ----------------------------------------------------
__global__ void zero_col_k() {
    int i = blockIdx.x * blockDim.x + threadIdx.x;
    if (i < MCOLS) { g_colcnt[i] = 0; g_colcur[i] = 0; }
}
__global__ void zero_row_k() {
    int i = threadIdx.x;
    if (i < NROWS) { g_rowcnt[i] = 0; g_rowcur[i] = 0; }
}

// ---------------- W_all pre-format (once): tf32, [k][136] padded -------------
__global__ void wprep_k(const float* __restrict__ W) {
    int i = blockIdx.x * 256 + threadIdx.x;   // grid 64
    if (i >= 128 * 128) return;
    int k = i >> 7, n = i & 127;
    g_Wfmt[k * 136 + n] = to_tf32(W[i]);
}

// ---------------- histograms -------------------------------------------------
__global__ void hist_col_k(const int* __restrict__ col_idx) {
    int e = blockIdx.x * blockDim.x + threadIdx.x;
    if (e < NNZ) atomicAdd(&g_colcnt[col_idx[e]], 1);
}
__global__ void hist_row_k(const int* __restrict__ row_idx) {  // grid 148
    __shared__ int h[NROWS];
    for (int i = threadIdx.x; i < NROWS; i += blockDim.x) h[i] = 0;
    __syncthreads();
    for (int e = blockIdx.x * blockDim.x + threadIdx.x; e < NNZ;
         e += gridDim.x * blockDim.x)
        atomicAdd(&h[row_idx[e]], 1);
    __syncthreads();
    for (int i = threadIdx.x; i < NROWS; i += blockDim.x) {
        int c = h[i];
        if (c) atomicAdd(&g_rowcnt[i], c);
    }
}

// ---------------- hierarchical column scan -----------------------------------
__global__ void scan1_k() {
    __shared__ int wsum[32];
    int i = blockIdx.x * 1024 + threadIdx.x;
    int lane = threadIdx.x & 31, wid = threadIdx.x >> 5;
    int v = (i < MCOLS) ? g_colcnt[i] : 0;
    #pragma unroll
    for (int off = 16; off > 0; off >>= 1) v += __shfl_down_sync(~0u, v, off);
    if (lane == 0) wsum[wid] = v;
    __syncthreads();
    if (wid == 0) {
        int s = wsum[lane];
        #pragma unroll
        for (int off = 16; off > 0; off >>= 1) s += __shfl_down_sync(~0u, s, off);
        if (lane == 0) g_partial[blockIdx.x] = s;
    }
}

__global__ void small_scan_k(const int* __restrict__ in, int* __restrict__ out, int n) {
    __shared__ int wsum[32];
    int tid = threadIdx.x, lane = tid & 31, wid = tid >> 5;
    int v = (tid < n) ? in[tid] : 0;
    int s = v;
    #pragma unroll
    for (int off = 1; off < 32; off <<= 1) {
        int t = __shfl_up_sync(~0u, s, off);
        if (lane >= off) s += t;
    }
    if (lane == 31) wsum[wid] = s;
    __syncthreads();
    if (wid == 0) {
        int ws = wsum[lane];
        #pragma unroll
        for (int off = 1; off < 32; off <<= 1) {
            int t = __shfl_up_sync(~0u, ws, off);
            if (lane >= off) ws += t;
        }
        wsum[lane] = ws;
    }
    __syncthreads();
    int excl = s - v + (wid > 0 ? wsum[wid - 1] : 0);
    if (tid < n) out[tid] = excl;
    if (tid == n - 1) out[n] = excl + v;
}

__global__ void scan3_k() {
    __shared__ int wsum[32];
    int i = blockIdx.x * 1024 + threadIdx.x;
    int lane = threadIdx.x & 31, wid = threadIdx.x >> 5;
    int v = (i < MCOLS) ? g_colcnt[i] : 0;
    int s = v;
    #pragma unroll
    for (int off = 1; off < 32; off <<= 1) {
        int t = __shfl_up_sync(~0u, s, off);
        if (lane >= off) s += t;
    }
    if (lane == 31) wsum[wid] = s;
    __syncthreads();
    if (wid == 0) {
        int ws = wsum[lane];
        #pragma unroll
        for (int off = 1; off < 32; off <<= 1) {
            int t = __shfl_up_sync(~0u, ws, off);
            if (lane >= off) ws += t;
        }
        wsum[lane] = ws;
    }
    __syncthreads();
    int excl = s - v + (wid > 0 ? wsum[wid - 1] : 0) + g_poff[blockIdx.x];
    if (i < MCOLS) g_coloff[i] = excl;
    if (i == MCOLS - 1) g_coloff[MCOLS] = excl + v;
}

// ---------------- scatters ---------------------------------------------------
__global__ void scatter_col_k(const int* __restrict__ col_idx) {
    int e = blockIdx.x * blockDim.x + threadIdx.x;
    if (e < NNZ) {
        int c = col_idx[e];
        int p = atomicAdd(&g_colcur[c], 1);
        g_colids[g_coloff[c] + p] = e;
    }
}
__global__ void scatter_row_k(const int* __restrict__ row_idx) {  // grid 148
    __shared__ int lcnt[NROWS];
    __shared__ int lbase[NROWS];
    const int tid = threadIdx.x;
    const int chunk = (NNZ + gridDim.x - 1) / gridDim.x;
    const int lo = blockIdx.x * chunk;
    const int hi = (lo + chunk < NNZ) ? lo + chunk : NNZ;

    for (int i = tid; i < NROWS; i += blockDim.x) lcnt[i] = 0;
    __syncthreads();
    for (int e = lo + tid; e < hi; e += blockDim.x)
        atomicAdd(&lcnt[row_idx[e]], 1);
    __syncthreads();
    for (int i = tid; i < NROWS; i += blockDim.x) {
        int c = lcnt[i];
        int b = c ? atomicAdd(&g_rowcur[i], c) : 0;
        lbase[i] = g_rowoff[i] + b;
        lcnt[i] = 0;
    }
    __syncthreads();
    for (int e = lo + tid; e < hi; e += blockDim.x) {
        int r = row_idx[e];
        int slot = atomicAdd(&lcnt[r], 1);
        g_rowids[lbase[r] + slot] = e;
    }
}

// ---------------- means ------------------------------------------------------
__global__ void colmean_k(const float* __restrict__ values) {
    int warp = (blockIdx.x * blockDim.x + threadIdx.x) >> 5;
    int lane = threadIdx.x & 31;
    if (warp >= MCOLS) return;
    int beg = g_coloff[warp], end = g_coloff[warp + 1];
    float4 acc = make_float4(0.f, 0.f, 0.f, 0.f);
    int j = beg;
    for (; j + 4 <= end; j += 4) {
        int e0 = g_colids[j], e1 = g_colids[j + 1];
        int e2 = g_colids[j + 2], e3 = g_colids[j + 3];
        float4 v0 = *(const float4*)(values + (size_t)e0 * D + lane * 4);
        float4 v1 = *(const float4*)(values + (size_t)e1 * D + lane * 4);
        float4 v2 = *(const float4*)(values + (size_t)e2 * D + lane * 4);
        float4 v3 = *(const float4*)(values + (size_t)e3 * D + lane * 4);
        acc.x += (v0.x + v1.x) + (v2.x + v3.x);
        acc.y += (v0.y + v1.y) + (v2.y + v3.y);
        acc.z += (v0.z + v1.z) + (v2.z + v3.z);
        acc.w += (v0.w + v1.w) + (v2.w + v3.w);
    }
    for (; j < end; j++) {
        int e = g_colids[j];
        float4 v = *(const float4*)(values + (size_t)e * D + lane * 4);
        acc.x += v.x; acc.y += v.y; acc.z += v.z; acc.w += v.w;
    }
    int n = end - beg;
    float inv = 1.0f / (float)(n > 1 ? n : 1);
    acc.x *= inv; acc.y *= inv; acc.z *= inv; acc.w *= inv;
    *(float4*)(g_colmean + (size_t)warp * D + lane * 4) = acc;
}

__global__ void rowmean_k(const float* __restrict__ values) {
    int r = blockIdx.x;
    int lane = threadIdx.x & 31, w = threadIdx.x >> 5;  // 8 warps
    int beg = g_rowoff[r], end = g_rowoff[r + 1];
    float4 acc = make_float4(0.f, 0.f, 0.f, 0.f);
    for (int j = beg + w; j < end; j += 8) {
        int e = g_rowids[j];
        float4 v = *(const float4*)(values + (size_t)e * D + lane * 4);
        acc.x += v.x; acc.y += v.y; acc.z += v.z; acc.w += v.w;
    }
    __shared__ float4 s[8][32];
    s[w][lane] = acc;
    __syncthreads();
    if (w == 0) {
        #pragma unroll
        for (int k = 1; k < 8; k++) {
            float4 t = s[k][lane];
            acc.x += t.x; acc.y += t.y; acc.z += t.z; acc.w += t.w;
        }
        *(float4*)(g_rowsum + (size_t)r * D + lane * 4) = acc;
        int n = end - beg;
        float inv = 1.0f / (float)(n > 1 ? n : 1);
        acc.x *= inv; acc.y *= inv; acc.z *= inv; acc.w *= inv;
        *(float4*)(g_rowmean + (size_t)r * D + lane * 4) = acc;
    }
}

// ---------------- global-mean + fused constant -------------------------------
__global__ void cconst_k(const float* __restrict__ W_both,
                         const float* __restrict__ b_all, const float* __restrict__ b_n,
                         const float* __restrict__ b_m,  const float* __restrict__ b_both) {
    __shared__ float gm[D];
    int t = threadIdx.x;
    float s = 0.f;
    for (int r = 0; r < NROWS; r++) s += g_rowsum[r * D + t];
    gm[t] = s * (1.0f / (float)NNZ);
    __syncthreads();
    float acc = 0.f;
    for (int k = 0; k < D; k++) acc += gm[k] * W_both[k * D + t];
    g_C[t] = 0.25f * (acc + b_all[t] + b_n[t] + b_m[t] + b_both[t]);
}

// ---------------- mma.sync tf32 primitive ------------------------------------
__device__ __forceinline__ void mma_tf32(float* c, const unsigned* a, unsigned b0, unsigned b1) {
    asm volatile(
        "mma.sync.aligned.m16n8k8.row.col.f32.tf32.tf32.f32 "
        "{%0,%1,%2,%3}, {%4,%5,%6,%7}, {%8,%9}, {%0,%1,%2,%3};"
        : "+f"(c[0]), "+f"(c[1]), "+f"(c[2]), "+f"(c[3])
        : "r"(a[0]), "r"(a[1]), "r"(a[2]), "r"(a[3]), "r"(b0), "r"(b1));
}

// ======== small GEMMs (G, H): out = 0.25*(A@W), validated path ===============
#define AS_STRIDE 68
#define WS_STRIDE 132
#define SMEM_AS   0
#define SMEM_WS   (128 * AS_STRIDE * 4)
#define SMEM_TOT  (SMEM_WS + 64 * WS_STRIDE * 4)

__global__ void __launch_bounds__(256, 2)
gemm_tc(const float* __restrict__ A, const float* __restrict__ W,
        float* __restrict__ out, int M) {
    extern __shared__ char smem[];
    float* As = (float*)(smem + SMEM_AS);
    float* Ws = (float*)(smem + SMEM_WS);

    const int tid  = threadIdx.x;
    const int lane = tid & 31;
    const int wid  = tid >> 5;
    const int g    = lane >> 2;
    const int t    = lane & 3;
    const int mw   = (wid & 3) * 32;
    const int nw   = (wid >> 2) * 64;
    const int m_base = blockIdx.x * 128;

    float acc[2][8][4];
    #pragma unroll
    for (int f = 0; f < 2; f++)
        #pragma unroll
        for (int nf = 0; nf < 8; nf++)
            #pragma unroll
            for (int i = 0; i < 4; i++) acc[f][nf][i] = 0.f;

    for (int kc = 0; kc < 128; kc += 64) {
        #pragma unroll
        for (int it = 0; it < 8; it++) {
            int i = it * 256 + tid;
            int m = i >> 4, kq = i & 15;
            int row = m_base + m;
            if (row >= M) row = M - 1;
            float4 v = *(const float4*)(A + (size_t)row * 128 + kc + kq * 4);
            unsigned* dst = (unsigned*)(As + m * AS_STRIDE + kq * 4);
            dst[0] = to_tf32(v.x); dst[1] = to_tf32(v.y);
            dst[2] = to_tf32(v.z); dst[3] = to_tf32(v.w);
        }
        #pragma unroll
        for (int it = 0; it < 8; it++) {
            int i = it * 256 + tid;
            int k = i >> 5, nq = i & 31;
            float4 v = *(const float4*)(W + (size_t)(kc + k) * 128 + nq * 4);
            unsigned* dst = (unsigned*)(Ws + k * WS_STRIDE + nq * 4);
            dst[0] = to_tf32(v.x); dst[1] = to_tf32(v.y);
            dst[2] = to_tf32(v.z); dst[3] = to_tf32(v.w);
        }
        __syncthreads();

        #pragma unroll
        for (int ks = 0; ks < 8; ks++) {
            int k0 = ks * 8;
            unsigned a[2][4];
            #pragma unroll
            for (int f = 0; f < 2; f++) {
                const unsigned* ap = (const unsigned*)(As + (mw + f * 16 + g) * AS_STRIDE + k0 + t);
                const unsigned* ap8 = ap + 8 * AS_STRIDE;
                a[f][0] = ap[0];  a[f][1] = ap8[0];
                a[f][2] = ap[4];  a[f][3] = ap8[4];
            }
            #pragma unroll
            for (int nf = 0; nf < 8; nf++) {
                int n = nw + nf * 8 + g;
                unsigned b0 = *(const unsigned*)(Ws + (k0 + t) * WS_STRIDE + n);
                unsigned b1 = *(const unsigned*)(Ws + (k0 + t + 4) * WS_STRIDE + n);
                mma_tf32(acc[0][nf], a[0], b0, b1);
                mma_tf32(acc[1][nf], a[1], b0, b1);
            }
        }
        __syncthreads();
    }

    #pragma unroll
    for (int f = 0; f < 2; f++) {
        #pragma unroll
        for (int nf = 0; nf < 8; nf++) {
            int nb = nw + nf * 8 + 2 * t;
            #pragma unroll
            for (int half = 0; half < 2; half++) {
                int m_loc = mw + f * 16 + g + half * 8;
                int e = m_base + m_loc;
                if (e >= M) continue;
                float2 o;
                o.x = acc[f][nf][half * 2 + 0] * 0.25f;
                o.y = acc[f][nf][half * 2 + 1] * 0.25f;
                *(float2*)(out + (size_t)e * 128 + nb) = o;
            }
        }
    }
}

// ======== persistent main GEMM: out = 0.25*(A@W_all) + G[col] + H[row] + C ===
// W resident in smem (tf32, stride 136 => conflict-free B frags: bank 8t+g).
// A double-buffered via cp.async (raw fp32, stride 132 => conflict-free 4g+t).
#define M_WS    0                         // Ws: 128*136*4 = 69632
#define M_AB0   69632                     // A buf0: 128*132*4 = 67584
#define M_AB1   137216                    // A buf1
#define M_IC    204800                    // sc[2][128]
#define M_IR    206848                    // sr[2][128]  (M_IC + 2048... see below)
#undef  M_IR
#define M_IC_SZ 1024
#define M_IRX   (M_IC + 2 * 512)          // 205824
#define M_CC    (M_IRX + 2 * 512)         // 206848
#define M_TOTAL (M_CC + 512)              // 207360

__device__ __forceinline__ void prefetch_tile(
    uint32_t sb, int buf, const float* __restrict__ A,
    const int* __restrict__ colidx, const int* __restrict__ rowidx,
    int m_base, int tid)
{
    uint32_t ab = sb + (buf ? M_AB1 : M_AB0);
    #pragma unroll
    for (int it = 0; it < 16; it++) {
        int i = it * 256 + tid;
        int r = i >> 5, c = i & 31;
        int row = m_base + r;
        if (row >= NNZ) row = NNZ - 1;
        CP_ASYNC16(ab + (uint32_t)(r * 528 + c * 16), A + (size_t)row * 128 + c * 4);
    }
    if (tid < 128) {
        int e = m_base + tid;
        if (e >= NNZ) e = NNZ - 1;
        CP_ASYNC4(sb + M_IC  + (uint32_t)(buf * 512 + tid * 4), colidx + e);
        CP_ASYNC4(sb + M_IRX + (uint32_t)(buf * 512 + tid * 4), rowidx + e);
    }
}

__global__ void __launch_bounds__(256, 1)
gemm_main(const float* __restrict__ A, float* __restrict__ out,
          const int* __restrict__ colidx, const int* __restrict__ rowidx) {
    extern __shared__ char smem[];
    const uint32_t sb = smem_to_u32(smem);
    const unsigned* Ws = (const unsigned*)smem;          // [128][136] tf32
    float* sCl = (float*)(smem + M_CC);
    const int tid = threadIdx.x, lane = tid & 31, w = tid >> 5;
    const int g = lane >> 2, t = lane & 3;
    const int mw = (w & 3) * 32, nw = (w >> 2) * 64;

    // prologue: W (preformatted tf32) + C into smem
    {
        const float4* src = (const float4*)g_Wfmt;       // 4352 float4
        float4* dst = (float4*)smem;
        #pragma unroll
        for (int it = 0; it < 17; it++) dst[it * 256 + tid] = src[it * 256 + tid];
        if (tid < 128) sCl[tid] = g_C[tid];
    }

    int tile = blockIdx.x;
    prefetch_tile(sb, 0, A, colidx, rowidx, tile * 128, tid);
    CP_COMMIT();

    int buf = 0;
    for (; tile < NTILES; tile += GRID_MAIN, buf ^= 1) {
        int nxt = tile + GRID_MAIN;
        if (nxt < NTILES)
            prefetch_tile(sb, buf ^ 1, A, colidx, rowidx, nxt * 128, tid);
        CP_COMMIT();
        CP_WAIT1();
        __syncthreads();

        const float* Ab = (const float*)(smem + (buf ? M_AB1 : M_AB0));

        float acc[2][8][4];
        #pragma unroll
        for (int f = 0; f < 2; f++)
            #pragma unroll
            for (int nf = 0; nf < 8; nf++)
                #pragma unroll
                for (int i = 0; i < 4; i++) acc[f][nf][i] = 0.f;

        #pragma unroll
        for (int ks = 0; ks < 16; ks++) {
            int k0 = ks * 8;
            unsigned a[2][4];
            #pragma unroll
            for (int f = 0; f < 2; f++) {
                const float* ap = Ab + (mw + f * 16 + g) * 132 + k0 + t;
                a[f][0] = to_tf32(ap[0]);
                a[f][1] = to_tf32(ap[8 * 132]);
                a[f][2] = to_tf32(ap[4]);
                a[f][3] = to_tf32(ap[8 * 132 + 4]);
            }
            #pragma unroll
            for (int nf = 0; nf < 8; nf++) {
                int n = nw + nf * 8 + g;
                unsigned b0 = Ws[(k0 + t) * 136 + n];
                unsigned b1 = Ws[(k0 + t + 4) * 136 + n];
                mma_tf32(acc[0][nf], a[0], b0, b1);
                mma_tf32(acc[1][nf], a[1], b0, b1);
            }
        }

        // epilogue (reads sc/sr of this buffer; must finish before next
        // iteration's prefetch overwrites them -> trailing __syncthreads)
        {
            const int* sc = (const int*)(smem + M_IC  + buf * 512);
            const int* sr = (const int*)(smem + M_IRX + buf * 512);
            int m_base = tile * 128;
            #pragma unroll
            for (int f = 0; f < 2; f++) {
                #pragma unroll
                for (int nf = 0; nf < 8; nf++) {
                    int nb = nw + nf * 8 + 2 * t;
                    #pragma unroll
                    for (int half = 0; half < 2; half++) {
                        int m_loc = mw + f * 16 + g + half * 8;
                        int e = m_base + m_loc;
                        if (e >= NNZ) continue;
                        float2 o;
                        o.x = acc[f][nf][half * 2 + 0] * 0.25f;
                        o.y = acc[f][nf][half * 2 + 1] * 0.25f;
                        int c = sc[m_loc], r = sr[m_loc];
                        float2 gv = *(const float2*)(g_G + (size_t)c * 128 + nb);
                        float2 hv = *(const float2*)(g_H + (size_t)r * 128 + nb);
                        o.x += gv.x + hv.x + sCl[nb];
                        o.y += gv.y + hv.y + sCl[nb + 1];
                        *(float2*)(out + (size_t)e * 128 + nb) = o;
                    }
                }
            }
        }
        __syncthreads();
    }
}

// ---------------------------------------------------------------------------
extern "C" void kernel_launch(void* const* d_in, const int* in_sizes, int n_in,
                              void* d_out, int out_size) {
    const float* values  = (const float*)d_in[0];
    const int*   row_idx = (const int*)  d_in[1];
    const int*   col_idx = (const int*)  d_in[2];
    const float* W_all   = (const float*)d_in[3];
    const float* b_all   = (const float*)d_in[4];
    const float* W_n     = (const float*)d_in[5];
    const float* b_n     = (const float*)d_in[6];
    const float* W_m     = (const float*)d_in[7];
    const float* b_m     = (const float*)d_in[8];
    const float* W_both  = (const float*)d_in[9];
    const float* b_both  = (const float*)d_in[10];
    float* out = (float*)d_out;

    static cudaStream_t s_col = nullptr, s_row = nullptr;
    static cudaEvent_t ev_fork = nullptr, ev_jc = nullptr, ev_jr = nullptr;
    if (!s_col) {
        cudaStreamCreateWithFlags(&s_col, cudaStreamNonBlocking);
        cudaStreamCreateWithFlags(&s_row, cudaStreamNonBlocking);
        cudaEventCreateWithFlags(&ev_fork, cudaEventDisableTiming);
        cudaEventCreateWithFlags(&ev_jc, cudaEventDisableTiming);
        cudaEventCreateWithFlags(&ev_jr, cudaEventDisableTiming);
        cudaFuncSetAttribute(gemm_tc,   cudaFuncAttributeMaxDynamicSharedMemorySize, SMEM_TOT);
        cudaFuncSetAttribute(gemm_main, cudaFuncAttributeMaxDynamicSharedMemorySize, M_TOTAL);
    }

    float* colmean_p; cudaGetSymbolAddress((void**)&colmean_p, g_colmean);
    float* rowmean_p; cudaGetSymbolAddress((void**)&rowmean_p, g_rowmean);
    float* G_p;       cudaGetSymbolAddress((void**)&G_p, g_G);
    float* H_p;       cudaGetSymbolAddress((void**)&H_p, g_H);
    int* partial_p;   cudaGetSymbolAddress((void**)&partial_p, g_partial);
    int* poff_p;      cudaGetSymbolAddress((void**)&poff_p, g_poff);
    int* rowcnt_p;    cudaGetSymbolAddress((void**)&rowcnt_p, g_rowcnt);
    int* rowoff_p;    cudaGetSymbolAddress((void**)&rowoff_p, g_rowoff);

    cudaEventRecord(ev_fork, 0);
    cudaStreamWaitEvent(s_col, ev_fork, 0);
    cudaStreamWaitEvent(s_row, ev_fork, 0);

    // ---- col chain (s_col) ----
    wprep_k<<<64, 256, 0, s_col>>>(W_all);
    zero_col_k<<<(MCOLS + 255) / 256, 256, 0, s_col>>>();
    hist_col_k<<<(NNZ + 255) / 256, 256, 0, s_col>>>(col_idx);
    scan1_k<<<SCAN_BLOCKS, 1024, 0, s_col>>>();
    small_scan_k<<<1, 1024, 0, s_col>>>(partial_p, poff_p, SCAN_BLOCKS);
    scan3_k<<<SCAN_BLOCKS, 1024, 0, s_col>>>();
    scatter_col_k<<<(NNZ + 255) / 256, 256, 0, s_col>>>(col_idx);
    colmean_k<<<(MCOLS * 32 + 255) / 256, 256, 0, s_col>>>(values);
    gemm_tc<<<(MCOLS + 127) / 128, 256, SMEM_TOT, s_col>>>(colmean_p, W_n, G_p, MCOLS);

    // ---- row chain (s_row) ----
    zero_row_k<<<1, 512, 0, s_row>>>();
    hist_row_k<<<148, 256, 0, s_row>>>(row_idx);
    small_scan_k<<<1, 1024, 0, s_row>>>(rowcnt_p, rowoff_p, NROWS);
    scatter_row_k<<<148, 256, 0, s_row>>>(row_idx);
    rowmean_k<<<NROWS, 256, 0, s_row>>>(values);
    cconst_k<<<1, 128, 0, s_row>>>(W_both, b_all, b_n, b_m, b_both);
    gemm_tc<<<(NROWS + 127) / 128, 256, SMEM_TOT, s_row>>>(rowmean_p, W_m, H_p, NROWS);

    // join, then persistent main GEMM
    cudaEventRecord(ev_jc, s_col);
    cudaEventRecord(ev_jr, s_row);
    cudaStreamWaitEvent(0, ev_jc, 0);
    cudaStreamWaitEvent(0, ev_jr, 0);
    gemm_main<<<GRID_MAIN, 256, M_TOTAL>>>(values, out, col_idx, row_idx);
}

// round 8
// speedup vs baseline: 1.6572x; 1.6572x over previous
#include <cuda_runtime.h>
#include <cstdint>

#define NNZ   1000000
#define NROWS 500
#define MCOLS 50000
#define D     128
#define SCAN_BLOCKS 49   // ceil(50000/1024)

// ---------------- scratch (device globals; no runtime allocation) ----------
__device__ float g_colmean[MCOLS * D];
__device__ float g_rowsum [NROWS * D];
__device__ float g_rowmean[NROWS * D];
__device__ float g_G[MCOLS * D];         // 0.25 * colmean @ W_n
__device__ float g_H[NROWS * D];         // 0.25 * rowmean @ W_m
__device__ float g_C[D];                 // 0.25*(gmean@W_both + all biases)
__device__ int   g_colcnt[MCOLS];
__device__ int   g_rowcnt[NROWS];
__device__ int   g_coloff[MCOLS + 1];
__device__ int   g_rowoff[NROWS + 1];
__device__ int   g_colcur[MCOLS];
__device__ int   g_rowcur[NROWS];
__device__ int   g_colids[NNZ];
__device__ int   g_rowids[NNZ];
__device__ int   g_partial[SCAN_BLOCKS];
__device__ int   g_poff[SCAN_BLOCKS + 1];
__device__ __align__(16) unsigned g_Wfmt[128 * 136];  // W_all tf32, [k][136] padded

__device__ __forceinline__ unsigned to_tf32(float f) {
    unsigned u;
    asm("cvt.rna.tf32.f32 %0, %1;" : "=r"(u) : "f"(f));
    return u;
}

// ---------------- zeroing ----------------------------------------------------
__global__ void zero_col_k() {
    int i = blockIdx.x * blockDim.x + threadIdx.x;
    if (i < MCOLS) { g_colcnt[i] = 0; g_colcur[i] = 0; }
}
__global__ void zero_row_k() {
    int i = threadIdx.x;
    if (i < NROWS) { g_rowcnt[i] = 0; g_rowcur[i] = 0; }
}

// ---------------- W_all pre-format (once): tf32, [k][136] padded -------------
__global__ void wprep_k(const float* __restrict__ W) {
    int i = blockIdx.x * 256 + threadIdx.x;   // grid 64
    if (i >= 128 * 128) return;
    int k = i >> 7, n = i & 127;
    g_Wfmt[k * 136 + n] = to_tf32(W[i]);
}

// ---------------- histograms -------------------------------------------------
__global__ void hist_col_k(const int* __restrict__ col_idx) {
    int e = blockIdx.x * blockDim.x + threadIdx.x;
    if (e < NNZ) atomicAdd(&g_colcnt[col_idx[e]], 1);
}
__global__ void hist_row_k(const int* __restrict__ row_idx) {  // grid 148
    __shared__ int h[NROWS];
    for (int i = threadIdx.x; i < NROWS; i += blockDim.x) h[i] = 0;
    __syncthreads();
    for (int e = blockIdx.x * blockDim.x + threadIdx.x; e < NNZ;
         e += gridDim.x * blockDim.x)
        atomicAdd(&h[row_idx[e]], 1);
    __syncthreads();
    for (int i = threadIdx.x; i < NROWS; i += blockDim.x) {
        int c = h[i];
        if (c) atomicAdd(&g_rowcnt[i], c);
    }
}

// ---------------- hierarchical column scan -----------------------------------
__global__ void scan1_k() {
    __shared__ int wsum[32];
    int i = blockIdx.x * 1024 + threadIdx.x;
    int lane = threadIdx.x & 31, wid = threadIdx.x >> 5;
    int v = (i < MCOLS) ? g_colcnt[i] : 0;
    #pragma unroll
    for (int off = 16; off > 0; off >>= 1) v += __shfl_down_sync(~0u, v, off);
    if (lane == 0) wsum[wid] = v;
    __syncthreads();
    if (wid == 0) {
        int s = wsum[lane];
        #pragma unroll
        for (int off = 16; off > 0; off >>= 1) s += __shfl_down_sync(~0u, s, off);
        if (lane == 0) g_partial[blockIdx.x] = s;
    }
}

__global__ void small_scan_k(const int* __restrict__ in, int* __restrict__ out, int n) {
    __shared__ int wsum[32];
    int tid = threadIdx.x, lane = tid & 31, wid = tid >> 5;
    int v = (tid < n) ? in[tid] : 0;
    int s = v;
    #pragma unroll
    for (int off = 1; off < 32; off <<= 1) {
        int t = __shfl_up_sync(~0u, s, off);
        if (lane >= off) s += t;
    }
    if (lane == 31) wsum[wid] = s;
    __syncthreads();
    if (wid == 0) {
        int ws = wsum[lane];
        #pragma unroll
        for (int off = 1; off < 32; off <<= 1) {
            int t = __shfl_up_sync(~0u, ws, off);
            if (lane >= off) ws += t;
        }
        wsum[lane] = ws;
    }
    __syncthreads();
    int excl = s - v + (wid > 0 ? wsum[wid - 1] : 0);
    if (tid < n) out[tid] = excl;
    if (tid == n - 1) out[n] = excl + v;
}

__global__ void scan3_k() {
    __shared__ int wsum[32];
    int i = blockIdx.x * 1024 + threadIdx.x;
    int lane = threadIdx.x & 31, wid = threadIdx.x >> 5;
    int v = (i < MCOLS) ? g_colcnt[i] : 0;
    int s = v;
    #pragma unroll
    for (int off = 1; off < 32; off <<= 1) {
        int t = __shfl_up_sync(~0u, s, off);
        if (lane >= off) s += t;
    }
    if (lane == 31) wsum[wid] = s;
    __syncthreads();
    if (wid == 0) {
        int ws = wsum[lane];
        #pragma unroll
        for (int off = 1; off < 32; off <<= 1) {
            int t = __shfl_up_sync(~0u, ws, off);
            if (lane >= off) ws += t;
        }
        wsum[lane] = ws;
    }
    __syncthreads();
    int excl = s - v + (wid > 0 ? wsum[wid - 1] : 0) + g_poff[blockIdx.x];
    if (i < MCOLS) g_coloff[i] = excl;
    if (i == MCOLS - 1) g_coloff[MCOLS] = excl + v;
}

// ---------------- scatters ---------------------------------------------------
__global__ void scatter_col_k(const int* __restrict__ col_idx) {
    int e = blockIdx.x * blockDim.x + threadIdx.x;
    if (e < NNZ) {
        int c = col_idx[e];
        int p = atomicAdd(&g_colcur[c], 1);
        g_colids[g_coloff[c] + p] = e;
    }
}
__global__ void scatter_row_k(const int* __restrict__ row_idx) {  // grid 148
    __shared__ int lcnt[NROWS];
    __shared__ int lbase[NROWS];
    const int tid = threadIdx.x;
    const int chunk = (NNZ + gridDim.x - 1) / gridDim.x;
    const int lo = blockIdx.x * chunk;
    const int hi = (lo + chunk < NNZ) ? lo + chunk : NNZ;

    for (int i = tid; i < NROWS; i += blockDim.x) lcnt[i] = 0;
    __syncthreads();
    for (int e = lo + tid; e < hi; e += blockDim.x)
        atomicAdd(&lcnt[row_idx[e]], 1);
    __syncthreads();
    for (int i = tid; i < NROWS; i += blockDim.x) {
        int c = lcnt[i];
        int b = c ? atomicAdd(&g_rowcur[i], c) : 0;
        lbase[i] = g_rowoff[i] + b;
        lcnt[i] = 0;
    }
    __syncthreads();
    for (int e = lo + tid; e < hi; e += blockDim.x) {
        int r = row_idx[e];
        int slot = atomicAdd(&lcnt[r], 1);
        g_rowids[lbase[r] + slot] = e;
    }
}

// ---------------- means ------------------------------------------------------
__global__ void colmean_k(const float* __restrict__ values) {
    int warp = (blockIdx.x * blockDim.x + threadIdx.x) >> 5;
    int lane = threadIdx.x & 31;
    if (warp >= MCOLS) return;
    int beg = g_coloff[warp], end = g_coloff[warp + 1];
    float4 acc = make_float4(0.f, 0.f, 0.f, 0.f);
    int j = beg;
    for (; j + 4 <= end; j += 4) {
        int e0 = g_colids[j], e1 = g_colids[j + 1];
        int e2 = g_colids[j + 2], e3 = g_colids[j + 3];
        float4 v0 = *(const float4*)(values + (size_t)e0 * D + lane * 4);
        float4 v1 = *(const float4*)(values + (size_t)e1 * D + lane * 4);
        float4 v2 = *(const float4*)(values + (size_t)e2 * D + lane * 4);
        float4 v3 = *(const float4*)(values + (size_t)e3 * D + lane * 4);
        acc.x += (v0.x + v1.x) + (v2.x + v3.x);
        acc.y += (v0.y + v1.y) + (v2.y + v3.y);
        acc.z += (v0.z + v1.z) + (v2.z + v3.z);
        acc.w += (v0.w + v1.w) + (v2.w + v3.w);
    }
    for (; j < end; j++) {
        int e = g_colids[j];
        float4 v = *(const float4*)(values + (size_t)e * D + lane * 4);
        acc.x += v.x; acc.y += v.y; acc.z += v.z; acc.w += v.w;
    }
    int n = end - beg;
    float inv = 1.0f / (float)(n > 1 ? n : 1);
    acc.x *= inv; acc.y *= inv; acc.z *= inv; acc.w *= inv;
    *(float4*)(g_colmean + (size_t)warp * D + lane * 4) = acc;
}

__global__ void rowmean_k(const float* __restrict__ values) {
    int r = blockIdx.x;
    int lane = threadIdx.x & 31, w = threadIdx.x >> 5;  // 8 warps
    int beg = g_rowoff[r], end = g_rowoff[r + 1];
    float4 acc = make_float4(0.f, 0.f, 0.f, 0.f);
    for (int j = beg + w; j < end; j += 8) {
        int e = g_rowids[j];
        float4 v = *(const float4*)(values + (size_t)e * D + lane * 4);
        acc.x += v.x; acc.y += v.y; acc.z += v.z; acc.w += v.w;
    }
    __shared__ float4 s[8][32];
    s[w][lane] = acc;
    __syncthreads();
    if (w == 0) {
        #pragma unroll
        for (int k = 1; k < 8; k++) {
            float4 t = s[k][lane];
            acc.x += t.x; acc.y += t.y; acc.z += t.z; acc.w += t.w;
        }
        *(float4*)(g_rowsum + (size_t)r * D + lane * 4) = acc;
        int n = end - beg;
        float inv = 1.0f / (float)(n > 1 ? n : 1);
        acc.x *= inv; acc.y *= inv; acc.z *= inv; acc.w *= inv;
        *(float4*)(g_rowmean + (size_t)r * D + lane * 4) = acc;
    }
}

// ---------------- global-mean + fused constant -------------------------------
__global__ void cconst_k(const float* __restrict__ W_both,
                         const float* __restrict__ b_all, const float* __restrict__ b_n,
                         const float* __restrict__ b_m,  const float* __restrict__ b_both) {
    __shared__ float gm[D];
    int t = threadIdx.x;
    float s = 0.f;
    for (int r = 0; r < NROWS; r++) s += g_rowsum[r * D + t];
    gm[t] = s * (1.0f / (float)NNZ);
    __syncthreads();
    float acc = 0.f;
    for (int k = 0; k < D; k++) acc += gm[k] * W_both[k * D + t];
    g_C[t] = 0.25f * (acc + b_all[t] + b_n[t] + b_m[t] + b_both[t]);
}

// ---------------- mma.sync tf32 primitive ------------------------------------
__device__ __forceinline__ void mma_tf32(float* c, const unsigned* a, unsigned b0, unsigned b1) {
    asm volatile(
        "mma.sync.aligned.m16n8k8.row.col.f32.tf32.tf32.f32 "
        "{%0,%1,%2,%3}, {%4,%5,%6,%7}, {%8,%9}, {%0,%1,%2,%3};"
        : "+f"(c[0]), "+f"(c[1]), "+f"(c[2]), "+f"(c[3])
        : "r"(a[0]), "r"(a[1]), "r"(a[2]), "r"(a[3]), "r"(b0), "r"(b1));
}

// ======== small GEMMs (G, H): out = 0.25*(A@W)  (validated R5 path) ==========
#define AS_STRIDE 68
#define WS_STRIDE 132
#define SMEM_AS   0
#define SMEM_WS   (128 * AS_STRIDE * 4)
#define SMEM_TOT  (SMEM_WS + 64 * WS_STRIDE * 4)

__global__ void __launch_bounds__(256, 2)
gemm_tc(const float* __restrict__ A, const float* __restrict__ W,
        float* __restrict__ out, int M) {
    extern __shared__ char smem[];
    float* As = (float*)(smem + SMEM_AS);
    float* Ws = (float*)(smem + SMEM_WS);

    const int tid  = threadIdx.x;
    const int lane = tid & 31;
    const int wid  = tid >> 5;
    const int g    = lane >> 2;
    const int t    = lane & 3;
    const int mw   = (wid & 3) * 32;
    const int nw   = (wid >> 2) * 64;
    const int m_base = blockIdx.x * 128;

    float acc[2][8][4];
    #pragma unroll
    for (int f = 0; f < 2; f++)
        #pragma unroll
        for (int nf = 0; nf < 8; nf++)
            #pragma unroll
            for (int i = 0; i < 4; i++) acc[f][nf][i] = 0.f;

    for (int kc = 0; kc < 128; kc += 64) {
        #pragma unroll
        for (int it = 0; it < 8; it++) {
            int i = it * 256 + tid;
            int m = i >> 4, kq = i & 15;
            int row = m_base + m;
            if (row >= M) row = M - 1;
            float4 v = *(const float4*)(A + (size_t)row * 128 + kc + kq * 4);
            unsigned* dst = (unsigned*)(As + m * AS_STRIDE + kq * 4);
            dst[0] = to_tf32(v.x); dst[1] = to_tf32(v.y);
            dst[2] = to_tf32(v.z); dst[3] = to_tf32(v.w);
        }
        #pragma unroll
        for (int it = 0; it < 8; it++) {
            int i = it * 256 + tid;
            int k = i >> 5, nq = i & 31;
            float4 v = *(const float4*)(W + (size_t)(kc + k) * 128 + nq * 4);
            unsigned* dst = (unsigned*)(Ws + k * WS_STRIDE + nq * 4);
            dst[0] = to_tf32(v.x); dst[1] = to_tf32(v.y);
            dst[2] = to_tf32(v.z); dst[3] = to_tf32(v.w);
        }
        __syncthreads();

        #pragma unroll
        for (int ks = 0; ks < 8; ks++) {
            int k0 = ks * 8;
            unsigned a[2][4];
            #pragma unroll
            for (int f = 0; f < 2; f++) {
                const unsigned* ap = (const unsigned*)(As + (mw + f * 16 + g) * AS_STRIDE + k0 + t);
                const unsigned* ap8 = ap + 8 * AS_STRIDE;
                a[f][0] = ap[0];  a[f][1] = ap8[0];
                a[f][2] = ap[4];  a[f][3] = ap8[4];
            }
            #pragma unroll
            for (int nf = 0; nf < 8; nf++) {
                int n = nw + nf * 8 + g;
                unsigned b0 = *(const unsigned*)(Ws + (k0 + t) * WS_STRIDE + n);
                unsigned b1 = *(const unsigned*)(Ws + (k0 + t + 4) * WS_STRIDE + n);
                mma_tf32(acc[0][nf], a[0], b0, b1);
                mma_tf32(acc[1][nf], a[1], b0, b1);
            }
        }
        __syncthreads();
    }

    #pragma unroll
    for (int f = 0; f < 2; f++) {
        #pragma unroll
        for (int nf = 0; nf < 8; nf++) {
            int nb = nw + nf * 8 + 2 * t;
            #pragma unroll
            for (int half = 0; half < 2; half++) {
                int m_loc = mw + f * 16 + g + half * 8;
                int e = m_base + m_loc;
                if (e >= M) continue;
                float2 o;
                o.x = acc[f][nf][half * 2 + 0] * 0.25f;
                o.y = acc[f][nf][half * 2 + 1] * 0.25f;
                *(float2*)(out + (size_t)e * 128 + nb) = o;
            }
        }
    }
}

// ======== main GEMM: out = 0.25*(A@W_all) + G[col] + H[row] + C ==============
// R5 structure (2 CTA/SM) + preformatted W (contiguous copy, no per-tile cvt)
// + Ws stride 136 (conflict-free B fragments).
#define WS2_STRIDE 136
#define MS_AS   0                              // 128*68*4  = 34816
#define MS_WS   (128 * AS_STRIDE * 4)          // 64*136*4  = 34816
#define MS_SC   (MS_WS + 64 * WS2_STRIDE * 4)  // 69632
#define MS_IC   (MS_SC + 512)
#define MS_IR   (MS_IC + 512)
#define MS_TOT  (MS_IR + 512)                  // 71168

__global__ void __launch_bounds__(256, 2)
gemm_tcm(const float* __restrict__ A, float* __restrict__ out, int M,
         const int* __restrict__ colidx, const int* __restrict__ rowidx) {
    extern __shared__ char smem[];
    float*    As = (float*)(smem + MS_AS);
    unsigned* Ws = (unsigned*)(smem + MS_WS);
    float* sC = (float*)(smem + MS_SC);
    int*   sc = (int*)  (smem + MS_IC);
    int*   sr = (int*)  (smem + MS_IR);

    const int tid  = threadIdx.x;
    const int lane = tid & 31;
    const int wid  = tid >> 5;
    const int g    = lane >> 2;
    const int t    = lane & 3;
    const int mw   = (wid & 3) * 32;
    const int nw   = (wid >> 2) * 64;
    const int m_base = blockIdx.x * 128;

    if (tid < 128) {
        int e = m_base + tid;
        if (e >= M) e = M - 1;
        sc[tid] = colidx[e];
        sr[tid] = rowidx[e];
        sC[tid] = g_C[tid];
    }

    float acc[2][8][4];
    #pragma unroll
    for (int f = 0; f < 2; f++)
        #pragma unroll
        for (int nf = 0; nf < 8; nf++)
            #pragma unroll
            for (int i = 0; i < 4; i++) acc[f][nf][i] = 0.f;

    for (int kc = 0; kc < 128; kc += 64) {
        // A chunk [128 m][64 k] -> As (cvt at store, validated layout)
        #pragma unroll
        for (int it = 0; it < 8; it++) {
            int i = it * 256 + tid;
            int m = i >> 4, kq = i & 15;
            int row = m_base + m;
            if (row >= M) row = M - 1;
            float4 v = *(const float4*)(A + (size_t)row * 128 + kc + kq * 4);
            unsigned* dst = (unsigned*)(As + m * AS_STRIDE + kq * 4);
            dst[0] = to_tf32(v.x); dst[1] = to_tf32(v.y);
            dst[2] = to_tf32(v.z); dst[3] = to_tf32(v.w);
        }
        // W chunk: contiguous copy of preformatted tf32 rows [kc..kc+64) x 136
        {
            const float4* src = (const float4*)(g_Wfmt + kc * WS2_STRIDE);
            float4* dst = (float4*)Ws;
            #pragma unroll
            for (int it = 0; it < 9; it++) {
                int i = it * 256 + tid;
                if (i < 64 * WS2_STRIDE / 4) dst[i] = src[i];
            }
        }
        __syncthreads();

        #pragma unroll
        for (int ks = 0; ks < 8; ks++) {
            int k0 = ks * 8;
            unsigned a[2][4];
            #pragma unroll
            for (int f = 0; f < 2; f++) {
                const unsigned* ap = (const unsigned*)(As + (mw + f * 16 + g) * AS_STRIDE + k0 + t);
                const unsigned* ap8 = ap + 8 * AS_STRIDE;
                a[f][0] = ap[0];  a[f][1] = ap8[0];
                a[f][2] = ap[4];  a[f][3] = ap8[4];
            }
            #pragma unroll
            for (int nf = 0; nf < 8; nf++) {
                int n = nw + nf * 8 + g;
                unsigned b0 = Ws[(k0 + t) * WS2_STRIDE + n];
                unsigned b1 = Ws[(k0 + t + 4) * WS2_STRIDE + n];
                mma_tf32(acc[0][nf], a[0], b0, b1);
                mma_tf32(acc[1][nf], a[1], b0, b1);
            }
        }
        __syncthreads();
    }

    #pragma unroll
    for (int f = 0; f < 2; f++) {
        #pragma unroll
        for (int nf = 0; nf < 8; nf++) {
            int nb = nw + nf * 8 + 2 * t;
            #pragma unroll
            for (int half = 0; half < 2; half++) {
                int m_loc = mw + f * 16 + g + half * 8;
                int e = m_base + m_loc;
                if (e >= M) continue;
                float2 o;
                o.x = acc[f][nf][half * 2 + 0] * 0.25f;
                o.y = acc[f][nf][half * 2 + 1] * 0.25f;
                int c = sc[m_loc], r = sr[m_loc];
                float2 gv = *(const float2*)(g_G + (size_t)c * 128 + nb);
                float2 hv = *(const float2*)(g_H + (size_t)r * 128 + nb);
                o.x += gv.x + hv.x + sC[nb];
                o.y += gv.y + hv.y + sC[nb + 1];
                *(float2*)(out + (size_t)e * 128 + nb) = o;
            }
        }
    }
}

// ---------------------------------------------------------------------------
extern "C" void kernel_launch(void* const* d_in, const int* in_sizes, int n_in,
                              void* d_out, int out_size) {
    const float* values  = (const float*)d_in[0];
    const int*   row_idx = (const int*)  d_in[1];
    const int*   col_idx = (const int*)  d_in[2];
    const float* W_all   = (const float*)d_in[3];
    const float* b_all   = (const float*)d_in[4];
    const float* W_n     = (const float*)d_in[5];
    const float* b_n     = (const float*)d_in[6];
    const float* W_m     = (const float*)d_in[7];
    const float* b_m     = (const float*)d_in[8];
    const float* W_both  = (const float*)d_in[9];
    const float* b_both  = (const float*)d_in[10];
    float* out = (float*)d_out;

    static cudaStream_t s_col = nullptr, s_row = nullptr;
    static cudaEvent_t ev_fork = nullptr, ev_jc = nullptr, ev_jr = nullptr;
    if (!s_col) {
        cudaStreamCreateWithFlags(&s_col, cudaStreamNonBlocking);
        cudaStreamCreateWithFlags(&s_row, cudaStreamNonBlocking);
        cudaEventCreateWithFlags(&ev_fork, cudaEventDisableTiming);
        cudaEventCreateWithFlags(&ev_jc, cudaEventDisableTiming);
        cudaEventCreateWithFlags(&ev_jr, cudaEventDisableTiming);
        cudaFuncSetAttribute(gemm_tc,  cudaFuncAttributeMaxDynamicSharedMemorySize, SMEM_TOT);
        cudaFuncSetAttribute(gemm_tcm, cudaFuncAttributeMaxDynamicSharedMemorySize, MS_TOT);
    }

    float* colmean_p; cudaGetSymbolAddress((void**)&colmean_p, g_colmean);
    float* rowmean_p; cudaGetSymbolAddress((void**)&rowmean_p, g_rowmean);
    float* G_p;       cudaGetSymbolAddress((void**)&G_p, g_G);
    float* H_p;       cudaGetSymbolAddress((void**)&H_p, g_H);
    int* partial_p;   cudaGetSymbolAddress((void**)&partial_p, g_partial);
    int* poff_p;      cudaGetSymbolAddress((void**)&poff_p, g_poff);
    int* rowcnt_p;    cudaGetSymbolAddress((void**)&rowcnt_p, g_rowcnt);
    int* rowoff_p;    cudaGetSymbolAddress((void**)&rowoff_p, g_rowoff);

    cudaEventRecord(ev_fork, 0);
    cudaStreamWaitEvent(s_col, ev_fork, 0);
    cudaStreamWaitEvent(s_row, ev_fork, 0);

    // ---- col chain (s_col) ----
    wprep_k<<<64, 256, 0, s_col>>>(W_all);
    zero_col_k<<<(MCOLS + 255) / 256, 256, 0, s_col>>>();
    hist_col_k<<<(NNZ + 255) / 256, 256, 0, s_col>>>(col_idx);
    scan1_k<<<SCAN_BLOCKS, 1024, 0, s_col>>>();
    small_scan_k<<<1, 1024, 0, s_col>>>(partial_p, poff_p, SCAN_BLOCKS);
    scan3_k<<<SCAN_BLOCKS, 1024, 0, s_col>>>();
    scatter_col_k<<<(NNZ + 255) / 256, 256, 0, s_col>>>(col_idx);
    colmean_k<<<(MCOLS * 32 + 255) / 256, 256, 0, s_col>>>(values);
    gemm_tc<<<(MCOLS + 127) / 128, 256, SMEM_TOT, s_col>>>(colmean_p, W_n, G_p, MCOLS);

    // ---- row chain (s_row) ----
    zero_row_k<<<1, 512, 0, s_row>>>();
    hist_row_k<<<148, 256, 0, s_row>>>(row_idx);
    small_scan_k<<<1, 1024, 0, s_row>>>(rowcnt_p, rowoff_p, NROWS);
    scatter_row_k<<<148, 256, 0, s_row>>>(row_idx);
    rowmean_k<<<NROWS, 256, 0, s_row>>>(values);
    cconst_k<<<1, 128, 0, s_row>>>(W_both, b_all, b_n, b_m, b_both);
    gemm_tc<<<(NROWS + 127) / 128, 256, SMEM_TOT, s_row>>>(rowmean_p, W_m, H_p, NROWS);

    // join, then main GEMM
    cudaEventRecord(ev_jc, s_col);
    cudaEventRecord(ev_jr, s_row);
    cudaStreamWaitEvent(0, ev_jc, 0);
    cudaStreamWaitEvent(0, ev_jr, 0);
    gemm_tcm<<<(NNZ + 127) / 128, 256, MS_TOT>>>(values, out, NNZ, col_idx, row_idx);
}